// round 3
// baseline (speedup 1.0000x reference)
#include <cuda_runtime.h>
#include <mma.h>
#include <math.h>

using namespace nvcuda;

#define SEQ   512
#define BATCH 128
#define EDIM  1024
#define HDIM  1024
#define GDIM  4096            // 4*H
#define MTOT  (SEQ * BATCH)   // 65536

// Scratch (device globals — no allocation allowed)
__device__ float g_xproj[(size_t)MTOT * GDIM];   // 1 GiB: precomputed x_t @ W_ih^T
__device__ float g_h[2][BATCH * HDIM];           // double-buffered hidden state
__device__ float g_c[BATCH * HDIM];              // cell state (in-place, per-column owner)

// ---------------------------------------------------------------------------
// Kernel 0: reset recurrent state (graph replays must be deterministic)
// ---------------------------------------------------------------------------
__global__ void zero_state_kernel() {
    int i = blockIdx.x * blockDim.x + threadIdx.x;
    if (i < BATCH * HDIM) { g_h[0][i] = 0.f; g_c[i] = 0.f; }
}

// ---------------------------------------------------------------------------
// Kernel 1: fused embedding gather + input projection
//   g_xproj[r][j] = sum_e embd[X[r]][e] * Wih[j][e]
// M=65536, N=4096, K=1024. Block tile 64x64, 4 warps (2x2), tf32 wmma m16n16k8.
// ---------------------------------------------------------------------------
__global__ void embed_proj_kernel(const int* __restrict__ X,
                                  const float* __restrict__ embd,
                                  const float* __restrict__ Wih) {
    __shared__ __align__(32) float As[64][24];   // [m][k], pad to 24 (32B-aligned frags)
    __shared__ __align__(32) float Bs[64][24];   // [n][k] (col_major for matrix_b)
    __shared__ int tok[64];

    const int bn  = blockIdx.x;      // 64 N-tiles
    const int bm  = blockIdx.y;      // 1024 M-tiles
    const int tid = threadIdx.x;     // 128 threads
    const int warp = tid >> 5;
    const int wm = warp >> 1;        // warp row (0/1) -> 32 M-rows
    const int wn = warp & 1;         // warp col (0/1) -> 32 N-cols

    if (tid < 64) tok[tid] = X[bm * 64 + tid];

    wmma::fragment<wmma::accumulator, 16, 16, 8, float> acc[2][2];
    #pragma unroll
    for (int i = 0; i < 2; i++)
        #pragma unroll
        for (int j = 0; j < 2; j++)
            wmma::fill_fragment(acc[i][j], 0.0f);

    for (int kc = 0; kc < EDIM; kc += 16) {
        __syncthreads();
        #pragma unroll
        for (int q = 0; q < 2; q++) {
            int slot = tid * 2 + q;          // 0..255
            int r    = slot >> 2;            // 0..63 (A row / B row)
            int kv   = slot & 3;             // float4 index within 16 K
            float4 va = *(const float4*)(embd + (size_t)tok[r] * EDIM + kc + kv * 4);
            *(float4*)&As[r][kv * 4] = va;
            float4 vb = *(const float4*)(Wih + (size_t)(bn * 64 + r) * EDIM + kc + kv * 4);
            *(float4*)&Bs[r][kv * 4] = vb;
        }
        __syncthreads();

        #pragma unroll
        for (int ks = 0; ks < 16; ks += 8) {
            wmma::fragment<wmma::matrix_a, 16, 16, 8, wmma::precision::tf32, wmma::row_major> af[2];
            wmma::fragment<wmma::matrix_b, 16, 16, 8, wmma::precision::tf32, wmma::col_major> bf[2];
            #pragma unroll
            for (int i = 0; i < 2; i++) {
                wmma::load_matrix_sync(af[i], &As[wm * 32 + i * 16][ks], 24);
                #pragma unroll
                for (int t = 0; t < af[i].num_elements; t++)
                    af[i].x[t] = wmma::__float_to_tf32(af[i].x[t]);
            }
            #pragma unroll
            for (int j = 0; j < 2; j++) {
                wmma::load_matrix_sync(bf[j], &Bs[wn * 32 + j * 16][ks], 24);
                #pragma unroll
                for (int t = 0; t < bf[j].num_elements; t++)
                    bf[j].x[t] = wmma::__float_to_tf32(bf[j].x[t]);
            }
            #pragma unroll
            for (int i = 0; i < 2; i++)
                #pragma unroll
                for (int j = 0; j < 2; j++)
                    wmma::mma_sync(acc[i][j], af[i], bf[j], acc[i][j]);
        }
    }

    #pragma unroll
    for (int i = 0; i < 2; i++)
        #pragma unroll
        for (int j = 0; j < 2; j++) {
            size_t row = (size_t)bm * 64 + wm * 32 + i * 16;
            size_t col = (size_t)bn * 64 + wn * 32 + j * 16;
            wmma::store_matrix_sync(g_xproj + row * GDIM + col, acc[i][j], GDIM,
                                    wmma::mem_row_major);
        }
}

// ---------------------------------------------------------------------------
// Kernel 2: one LSTM step (fused recurrent GEMM + gates + state update).
// Grid (2, 64): blockIdx.x = batch half (64 rows), blockIdx.y = 16 hidden cols.
// Block computes, for its 16 hidden cols, all 4 gate tiles [64 x 16] of
// h_in @ W_hh^T, adds precomputed input projection + biases, updates c/h.
// 8 warps: warp = (wm in {0,1}) x (gate in {0..3}); each warp 2 m-frags.
// ---------------------------------------------------------------------------
__global__ void lstm_step_kernel(const float* __restrict__ Whh,
                                 const float* __restrict__ bih,
                                 const float* __restrict__ bhh,
                                 int s) {
    __shared__ __align__(32) float smem[5120];               // 20480 B, overlaid
    float (*Hs)[24]     = (float(*)[24])smem;                // [64 m][24 k]
    float (*Ws)[16][24] = (float(*)[16][24])(smem + 1536);   // [4 g][16 n][24 k]
    float (*Gs)[64][20] = (float(*)[64][20])smem;            // [4 g][64 m][20 n] (after GEMM)

    const float* hin = g_h[s & 1];
    float*       hout = g_h[(s + 1) & 1];
    const int b0  = blockIdx.x * 64;
    const int c0  = blockIdx.y * 16;
    const int tid = threadIdx.x;        // 256
    const int warp = tid >> 5;
    const int wg = warp & 3;            // gate index
    const int wm = warp >> 2;           // 0/1: which 32 batch rows

    wmma::fragment<wmma::accumulator, 16, 16, 8, float> acc[2];
    #pragma unroll
    for (int i = 0; i < 2; i++) wmma::fill_fragment(acc[i], 0.0f);

    for (int kc = 0; kc < HDIM; kc += 16) {
        __syncthreads();
        {   // Hs: 64 rows x 16 K  (256 float4 slots, 1/thread)
            int m = tid >> 2, kv = tid & 3;
            *(float4*)&Hs[m][kv * 4] =
                *(const float4*)(hin + (size_t)(b0 + m) * HDIM + kc + kv * 4);
        }
        {   // Ws: 4 gates x 16 n-cols x 16 K  (256 float4 slots)
            int nr = tid >> 2, kv = tid & 3;   // nr 0..63
            int g = nr >> 4, n = nr & 15;
            *(float4*)&Ws[g][n][kv * 4] =
                *(const float4*)(Whh + (size_t)(g * HDIM + c0 + n) * HDIM + kc + kv * 4);
        }
        __syncthreads();

        #pragma unroll
        for (int ks = 0; ks < 16; ks += 8) {
            wmma::fragment<wmma::matrix_b, 16, 16, 8, wmma::precision::tf32, wmma::col_major> bf;
            wmma::load_matrix_sync(bf, &Ws[wg][0][ks], 24);
            #pragma unroll
            for (int t = 0; t < bf.num_elements; t++)
                bf.x[t] = wmma::__float_to_tf32(bf.x[t]);
            #pragma unroll
            for (int i = 0; i < 2; i++) {
                wmma::fragment<wmma::matrix_a, 16, 16, 8, wmma::precision::tf32, wmma::row_major> af;
                wmma::load_matrix_sync(af, &Hs[wm * 32 + i * 16][ks], 24);
                #pragma unroll
                for (int t = 0; t < af.num_elements; t++)
                    af.x[t] = wmma::__float_to_tf32(af.x[t]);
                wmma::mma_sync(acc[i], af, bf, acc[i]);
            }
        }
    }

    __syncthreads();   // GEMM phase done; safe to overlay Gs over Hs/Ws
    #pragma unroll
    for (int i = 0; i < 2; i++)
        wmma::store_matrix_sync(&Gs[wg][wm * 32 + i * 16][0], acc[i], 20,
                                wmma::mem_row_major);
    __syncthreads();

    // Epilogue: gates -> activations -> c/h update. 64*16 = 1024 cells, 4/thread.
    #pragma unroll
    for (int p = 0; p < 4; p++) {
        int idx = p * 256 + tid;
        int bl  = idx >> 4;              // local batch row 0..63
        int col = idx & 15;              // local hidden col 0..15
        int b   = b0 + bl;
        int hc  = c0 + col;
        size_t xb = ((size_t)(s * BATCH + b)) * GDIM + hc;

        float gi = Gs[0][bl][col] + g_xproj[xb]            + bih[hc]            + bhh[hc];
        float gf = Gs[1][bl][col] + g_xproj[xb + HDIM]     + bih[HDIM + hc]     + bhh[HDIM + hc];
        float gg = Gs[2][bl][col] + g_xproj[xb + 2*HDIM]   + bih[2*HDIM + hc]   + bhh[2*HDIM + hc];
        float go = Gs[3][bl][col] + g_xproj[xb + 3*HDIM]   + bih[3*HDIM + hc]   + bhh[3*HDIM + hc];

        float iv = 1.f / (1.f + expf(-gi));
        float fv = 1.f / (1.f + expf(-gf));
        float ov = 1.f / (1.f + expf(-go));

        size_t ci = (size_t)b * HDIM + hc;
        float cn = fv * g_c[ci] + iv * tanhf(gg);
        float hn = ov * tanhf(cn);
        g_c[ci]  = cn;
        hout[ci] = hn;
    }
}

// ---------------------------------------------------------------------------
// Kernel 3: log_softmax over the BATCH axis of h_last [128, 1024].
// One block per hidden column; 128 threads = batch entries.
// ---------------------------------------------------------------------------
__global__ void logsoftmax_kernel(float* __restrict__ out) {
    const float* h = g_h[0];     // after 512 steps, last write went to buffer 0
    const int hj = blockIdx.x;
    const int t  = threadIdx.x;  // 128

    float v = h[(size_t)t * HDIM + hj];

    __shared__ float rm[4], rs[4];
    float m = v;
    #pragma unroll
    for (int o = 16; o; o >>= 1) m = fmaxf(m, __shfl_xor_sync(0xffffffffu, m, o));
    if ((t & 31) == 0) rm[t >> 5] = m;
    __syncthreads();
    m = fmaxf(fmaxf(rm[0], rm[1]), fmaxf(rm[2], rm[3]));

    float e = expf(v - m);
    float ssum = e;
    #pragma unroll
    for (int o = 16; o; o >>= 1) ssum += __shfl_xor_sync(0xffffffffu, ssum, o);
    if ((t & 31) == 0) rs[t >> 5] = ssum;
    __syncthreads();
    ssum = rs[0] + rs[1] + rs[2] + rs[3];

    out[(size_t)t * HDIM + hj] = (v - m) - logf(ssum);
}

// ---------------------------------------------------------------------------
extern "C" void kernel_launch(void* const* d_in, const int* in_sizes, int n_in,
                              void* d_out, int out_size) {
    (void)in_sizes; (void)n_in; (void)out_size;
    const int*   X    = (const int*)d_in[0];
    const float* embd = (const float*)d_in[1];
    const float* Wih  = (const float*)d_in[2];
    const float* Whh  = (const float*)d_in[3];
    const float* bih  = (const float*)d_in[4];
    const float* bhh  = (const float*)d_in[5];
    float* out = (float*)d_out;

    zero_state_kernel<<<512, 256>>>();
    embed_proj_kernel<<<dim3(64, 1024), 128>>>(X, embd, Wih);
    for (int s = 0; s < SEQ; s++)
        lstm_step_kernel<<<dim3(2, 64), 256>>>(Whh, bih, bhh, s);
    logsoftmax_kernel<<<HDIM, BATCH>>>(out);
}

// round 4
// speedup vs baseline: 1.4379x; 1.4379x over previous
#include <cuda_runtime.h>
#include <mma.h>
#include <math.h>

using namespace nvcuda;

#define SEQ   512
#define BATCH 128
#define EDIM  1024
#define HDIM  1024
#define GDIM  4096            // 4*H
#define MTOT  (SEQ * BATCH)   // 65536
#define GRID  128             // persistent blocks (<= 148 SMs, 1 block/SM via smem)

// Scratch (device globals — no allocation allowed)
__device__ float g_xproj[(size_t)MTOT * GDIM];   // 1 GiB: precomputed x_t @ W_ih^T
__device__ float g_h[2][BATCH * HDIM];           // double-buffered hidden state
__device__ float g_c[BATCH * HDIM];              // cell state (block-private slices)
__device__ unsigned g_arrive;                    // grid-barrier arrival counter

// smem layout constants (floats)
#define WS_LD   1028                 // 32 rows x 1028 (pad: 2-way-conflict max)
#define HS_LD   132                  // 128 rows x 132
#define GS_LD   36                   // epilogue staging, overlays Hs
#define SMEM_FLOATS (32 * WS_LD + 128 * HS_LD)   // 32896 + 16896 = 49792 fl = 199168 B

// ---------------------------------------------------------------------------
// Kernel 0: reset recurrent state + grid barrier (graph replays deterministic)
// ---------------------------------------------------------------------------
__global__ void zero_state_kernel() {
    int i = blockIdx.x * blockDim.x + threadIdx.x;
    if (i < BATCH * HDIM) { g_h[0][i] = 0.f; g_c[i] = 0.f; }
    if (i == 0) g_arrive = 0u;
}

// ---------------------------------------------------------------------------
// Kernel 1: fused embedding gather + input projection (unchanged from R3)
//   g_xproj[r][j] = sum_e embd[X[r]][e] * Wih[j][e]
// ---------------------------------------------------------------------------
__global__ void embed_proj_kernel(const int* __restrict__ X,
                                  const float* __restrict__ embd,
                                  const float* __restrict__ Wih) {
    __shared__ __align__(32) float As[64][24];
    __shared__ __align__(32) float Bs[64][24];
    __shared__ int tok[64];

    const int bn  = blockIdx.x;      // 64 N-tiles
    const int bm  = blockIdx.y;      // 1024 M-tiles
    const int tid = threadIdx.x;     // 128 threads
    const int warp = tid >> 5;
    const int wm = warp >> 1;
    const int wn = warp & 1;

    if (tid < 64) tok[tid] = X[bm * 64 + tid];

    wmma::fragment<wmma::accumulator, 16, 16, 8, float> acc[2][2];
    #pragma unroll
    for (int i = 0; i < 2; i++)
        #pragma unroll
        for (int j = 0; j < 2; j++)
            wmma::fill_fragment(acc[i][j], 0.0f);

    for (int kc = 0; kc < EDIM; kc += 16) {
        __syncthreads();
        #pragma unroll
        for (int q = 0; q < 2; q++) {
            int slot = tid * 2 + q;
            int r    = slot >> 2;
            int kv   = slot & 3;
            float4 va = *(const float4*)(embd + (size_t)tok[r] * EDIM + kc + kv * 4);
            *(float4*)&As[r][kv * 4] = va;
            float4 vb = *(const float4*)(Wih + (size_t)(bn * 64 + r) * EDIM + kc + kv * 4);
            *(float4*)&Bs[r][kv * 4] = vb;
        }
        __syncthreads();

        #pragma unroll
        for (int ks = 0; ks < 16; ks += 8) {
            wmma::fragment<wmma::matrix_a, 16, 16, 8, wmma::precision::tf32, wmma::row_major> af[2];
            wmma::fragment<wmma::matrix_b, 16, 16, 8, wmma::precision::tf32, wmma::col_major> bf[2];
            #pragma unroll
            for (int i = 0; i < 2; i++) {
                wmma::load_matrix_sync(af[i], &As[wm * 32 + i * 16][ks], 24);
                #pragma unroll
                for (int t = 0; t < af[i].num_elements; t++)
                    af[i].x[t] = wmma::__float_to_tf32(af[i].x[t]);
            }
            #pragma unroll
            for (int j = 0; j < 2; j++) {
                wmma::load_matrix_sync(bf[j], &Bs[wn * 32 + j * 16][ks], 24);
                #pragma unroll
                for (int t = 0; t < bf[j].num_elements; t++)
                    bf[j].x[t] = wmma::__float_to_tf32(bf[j].x[t]);
            }
            #pragma unroll
            for (int i = 0; i < 2; i++)
                #pragma unroll
                for (int j = 0; j < 2; j++)
                    wmma::mma_sync(acc[i][j], af[i], bf[j], acc[i][j]);
        }
    }

    #pragma unroll
    for (int i = 0; i < 2; i++)
        #pragma unroll
        for (int j = 0; j < 2; j++) {
            size_t row = (size_t)bm * 64 + wm * 32 + i * 16;
            size_t col = (size_t)bn * 64 + wn * 32 + j * 16;
            wmma::store_matrix_sync(g_xproj + row * GDIM + col, acc[i][j], GDIM,
                                    wmma::mem_row_major);
        }
}

// ---------------------------------------------------------------------------
// Kernel 2: PERSISTENT LSTM. One launch runs all 512 steps.
// 128 blocks x 256 threads. Block bx owns hidden cols [bx*8, bx*8+8) and keeps
// the 32 corresponding W_hh rows (4 gates x 8 cols) resident in smem as tf32.
// Per step: stream h (tf32-converted into smem), wmma GEMM 128x32x1024,
// fused gate epilogue + c/h update, then a grid barrier.
// ---------------------------------------------------------------------------
__global__ void __launch_bounds__(256, 1)
lstm_persistent_kernel(const float* __restrict__ Whh,
                       const float* __restrict__ bih,
                       const float* __restrict__ bhh) {
    extern __shared__ __align__(16) float smem[];
    float* Ws = smem;                   // [32][WS_LD]
    float* Hs = smem + 32 * WS_LD;      // [128][HS_LD]
    float* Gs = Hs;                     // [128][GS_LD] epilogue overlay
    __shared__ float bsum[32];

    const int c0   = blockIdx.x * 8;    // first owned hidden column
    const int tid  = threadIdx.x;       // 256
    const int warp = tid >> 5;          // 8 warps
    const int wm   = warp >> 1;         // 0..3 : 32 batch rows each
    const int wn   = warp & 1;          // 0..1 : 16 gate-cols each

    // ---- load W_hh slice into smem, pre-converted to tf32 ----
    for (int i = tid; i < 32 * 256; i += 256) {       // 8192 float4
        int n  = i >> 8;                              // 0..31
        int kv = i & 255;
        int g = n >> 3, col = n & 7;
        float4 v = *(const float4*)(Whh + (size_t)(g * HDIM + c0 + col) * HDIM + kv * 4);
        float* dst = Ws + n * WS_LD + kv * 4;
        dst[0] = wmma::__float_to_tf32(v.x);
        dst[1] = wmma::__float_to_tf32(v.y);
        dst[2] = wmma::__float_to_tf32(v.z);
        dst[3] = wmma::__float_to_tf32(v.w);
    }
    if (tid < 32) {
        int g = tid >> 3, col = tid & 7;
        int r = g * HDIM + c0 + col;
        bsum[tid] = bih[r] + bhh[r];
    }
    __syncthreads();

    for (int s = 0; s < SEQ; s++) {
        const float* hin  = g_h[s & 1];
        float*       hout = g_h[(s + 1) & 1];

        wmma::fragment<wmma::accumulator, 16, 16, 8, float> acc[2];
        #pragma unroll
        for (int i = 0; i < 2; i++) wmma::fill_fragment(acc[i], 0.0f);

        for (int kc = 0; kc < HDIM; kc += 128) {
            __syncthreads();
            // stage h[128][128] chunk, tf32-converted. 4096 float4, 16/thread.
            #pragma unroll
            for (int j = 0; j < 16; j++) {
                int slot = tid + j * 256;
                int b  = slot >> 5;
                int kv = slot & 31;
                float4 v = __ldcg((const float4*)(hin + (size_t)b * HDIM + kc + kv * 4));
                float* dst = Hs + b * HS_LD + kv * 4;
                dst[0] = wmma::__float_to_tf32(v.x);
                dst[1] = wmma::__float_to_tf32(v.y);
                dst[2] = wmma::__float_to_tf32(v.z);
                dst[3] = wmma::__float_to_tf32(v.w);
            }
            __syncthreads();

            #pragma unroll
            for (int ks = 0; ks < 128; ks += 8) {
                wmma::fragment<wmma::matrix_b, 16, 16, 8, wmma::precision::tf32, wmma::col_major> bf;
                wmma::load_matrix_sync(bf, Ws + (wn * 16) * WS_LD + kc + ks, WS_LD);
                #pragma unroll
                for (int i = 0; i < 2; i++) {
                    wmma::fragment<wmma::matrix_a, 16, 16, 8, wmma::precision::tf32, wmma::row_major> af;
                    wmma::load_matrix_sync(af, Hs + (wm * 32 + i * 16) * HS_LD + ks, HS_LD);
                    wmma::mma_sync(acc[i], af, bf, acc[i]);
                }
            }
        }

        // ---- stage gates, fused epilogue ----
        __syncthreads();
        #pragma unroll
        for (int i = 0; i < 2; i++)
            wmma::store_matrix_sync(Gs + (wm * 32 + i * 16) * GS_LD + wn * 16, acc[i],
                                    GS_LD, wmma::mem_row_major);
        __syncthreads();

        #pragma unroll
        for (int p = 0; p < 4; p++) {
            int idx = p * 256 + tid;          // 0..1023
            int bl  = idx >> 3;               // batch row 0..127
            int col = idx & 7;                // owned hidden col 0..7
            int hc  = c0 + col;
            size_t xb = ((size_t)(s * BATCH + bl)) * GDIM + hc;

            float gi = Gs[bl * GS_LD +      col] + g_xproj[xb]              + bsum[     col];
            float gf = Gs[bl * GS_LD +  8 + col] + g_xproj[xb +     HDIM]   + bsum[ 8 + col];
            float gg = Gs[bl * GS_LD + 16 + col] + g_xproj[xb + 2 * HDIM]   + bsum[16 + col];
            float go = Gs[bl * GS_LD + 24 + col] + g_xproj[xb + 3 * HDIM]   + bsum[24 + col];

            float iv = 1.f / (1.f + expf(-gi));
            float fv = 1.f / (1.f + expf(-gf));
            float ov = 1.f / (1.f + expf(-go));

            size_t ci = (size_t)bl * HDIM + hc;
            float cn = fv * g_c[ci] + iv * tanhf(gg);
            float hn = ov * tanhf(cn);
            g_c[ci]  = cn;
            hout[ci] = hn;
        }

        // ---- grid barrier (skip after last step) ----
        if (s != SEQ - 1) {
            __syncthreads();
            if (tid == 0) {
                __threadfence();
                atomicAdd(&g_arrive, 1u);
                unsigned target = (unsigned)(s + 1) * (unsigned)GRID;
                while (atomicAdd(&g_arrive, 0u) < target) __nanosleep(32);
                __threadfence();
            }
            __syncthreads();
        }
    }
}

// ---------------------------------------------------------------------------
// Kernel 3: log_softmax over the BATCH axis of h_last [128, 1024].
// ---------------------------------------------------------------------------
__global__ void logsoftmax_kernel(float* __restrict__ out) {
    const float* h = g_h[0];     // SEQ even -> final write landed in buffer 0
    const int hj = blockIdx.x;
    const int t  = threadIdx.x;  // 128

    float v = h[(size_t)t * HDIM + hj];

    __shared__ float rm[4], rs[4];
    float m = v;
    #pragma unroll
    for (int o = 16; o; o >>= 1) m = fmaxf(m, __shfl_xor_sync(0xffffffffu, m, o));
    if ((t & 31) == 0) rm[t >> 5] = m;
    __syncthreads();
    m = fmaxf(fmaxf(rm[0], rm[1]), fmaxf(rm[2], rm[3]));

    float e = expf(v - m);
    float ssum = e;
    #pragma unroll
    for (int o = 16; o; o >>= 1) ssum += __shfl_xor_sync(0xffffffffu, ssum, o);
    if ((t & 31) == 0) rs[t >> 5] = ssum;
    __syncthreads();
    ssum = rs[0] + rs[1] + rs[2] + rs[3];

    out[(size_t)t * HDIM + hj] = (v - m) - logf(ssum);
}

// ---------------------------------------------------------------------------
extern "C" void kernel_launch(void* const* d_in, const int* in_sizes, int n_in,
                              void* d_out, int out_size) {
    (void)in_sizes; (void)n_in; (void)out_size;
    const int*   X    = (const int*)d_in[0];
    const float* embd = (const float*)d_in[1];
    const float* Wih  = (const float*)d_in[2];
    const float* Whh  = (const float*)d_in[3];
    const float* bih  = (const float*)d_in[4];
    const float* bhh  = (const float*)d_in[5];
    float* out = (float*)d_out;

    static int smem_configured = 0;
    if (!smem_configured) {
        cudaFuncSetAttribute(lstm_persistent_kernel,
                             cudaFuncAttributeMaxDynamicSharedMemorySize,
                             SMEM_FLOATS * sizeof(float));
        smem_configured = 1;
    }

    zero_state_kernel<<<512, 256>>>();
    embed_proj_kernel<<<dim3(64, 1024), 128>>>(X, embd, Wih);
    lstm_persistent_kernel<<<GRID, 256, SMEM_FLOATS * sizeof(float)>>>(Whh, bih, bhh);
    logsoftmax_kernel<<<HDIM, BATCH>>>(out);
}

// round 5
// speedup vs baseline: 3.2046x; 2.2286x over previous
#include <cuda_runtime.h>
#include <cuda_bf16.h>
#include <mma.h>
#include <math.h>

using namespace nvcuda;

#define SEQ   512
#define BATCH 128
#define EDIM  1024
#define HDIM  1024
#define GDIM  4096
#define GRID  128            // persistent blocks, 1/SM via smem

// ---- device scratch (no allocations allowed) ----
__device__ float g_xq[(size_t)SEQ * GDIM * BATCH];      // [s][gate*H+hc][b] fp32 (1 GiB), transposed for coalesced epilogue reads
__device__ __nv_bfloat16 g_hb[2][BATCH * HDIM];         // bf16 hidden state, double buffered, [b][hc]
__device__ float g_hf[BATCH * HDIM];                    // fp32 final hidden state (written at last step only)
__device__ float g_c[HDIM * BATCH];                     // fp32 cell state, transposed [hc][b]
__device__ unsigned g_arrive;                           // grid barrier counter

// persistent-kernel smem layout (elements)
#define WS_LD 1040           // 32 rows of W_hh slice, pad: row stride 2080B -> +8 banks
#define HS_LD 264            // 128 rows of h chunk (256 K), row stride 528B -> +4 banks
#define GS_LD 36
#define PERS_SMEM_BYTES (32 * WS_LD * 2 + 2 * 128 * HS_LD * 2)   // 66560 + 135168 = 201728

__device__ __forceinline__ unsigned sptr(const void* p) {
    return (unsigned)__cvta_generic_to_shared(p);
}

// ---------------------------------------------------------------------------
// Kernel 0: reset state (deterministic across graph replays)
// ---------------------------------------------------------------------------
__global__ void zero_state_kernel() {
    int i = blockIdx.x * blockDim.x + threadIdx.x;     // 131072 threads
    if (i < BATCH * HDIM / 2)
        ((unsigned*)g_hb[0])[i] = 0u;                  // zero bf16 h buffer 0
    if (i < HDIM * BATCH)
        g_c[i] = 0.f;
    if (i == 0) g_arrive = 0u;
}

// ---------------------------------------------------------------------------
// Kernel 1: embedding gather + input projection, bf16 wmma, 128x128 tiles.
//   writes g_xq[s][n][b] = sum_e emb[X[s,b]][e] * Wih[n][e]   (transposed!)
// grid (32 n-tiles, 512 timesteps), 256 threads, warp tile 64m x 32n.
// ---------------------------------------------------------------------------
__global__ __launch_bounds__(256)
void embed_proj_kernel(const int* __restrict__ X,
                       const float* __restrict__ embd,
                       const float* __restrict__ Wih) {
    __shared__ __align__(16) __nv_bfloat16 As[2][128][40];   // [m][k] row stride 80B
    __shared__ __align__(16) __nv_bfloat16 Bs[2][128][40];   // [n][k]
    __shared__ int tok[128];

    const int s   = blockIdx.y;
    const int nt  = blockIdx.x;
    const int tid = threadIdx.x;
    const int warp = tid >> 5;
    const int wm = warp >> 2;         // 0..1 -> 64 m rows
    const int wn = warp & 3;          // 0..3 -> 32 n cols

    if (tid < 128) tok[tid] = X[s * 128 + tid];
    __syncthreads();

    wmma::fragment<wmma::accumulator, 16, 16, 16, float> acc[4][2];
    #pragma unroll
    for (int i = 0; i < 4; i++)
        #pragma unroll
        for (int j = 0; j < 2; j++) wmma::fill_fragment(acc[i][j], 0.0f);

    // per-thread chunk slots: 4 float4 of A, 4 of B per 32-K chunk
    int rr[4], kk[4];
    #pragma unroll
    for (int q = 0; q < 4; q++) {
        int slot = q * 256 + tid;
        rr[q] = slot >> 3;            // row 0..127
        kk[q] = slot & 7;             // float4 index within 32 K
    }

    float4 ra[4], rb[4];
    auto ldg_chunk = [&](int kc) {
        #pragma unroll
        for (int q = 0; q < 4; q++) {
            ra[q] = *(const float4*)(embd + (size_t)tok[rr[q]] * EDIM + kc * 32 + kk[q] * 4);
            rb[q] = *(const float4*)(Wih + (size_t)(nt * 128 + rr[q]) * EDIM + kc * 32 + kk[q] * 4);
        }
    };
    auto sts_chunk = [&](int buf) {
        #pragma unroll
        for (int q = 0; q < 4; q++) {
            __nv_bfloat162 a0 = __floats2bfloat162_rn(ra[q].x, ra[q].y);
            __nv_bfloat162 a1 = __floats2bfloat162_rn(ra[q].z, ra[q].w);
            uint2 ua = make_uint2(*(unsigned*)&a0, *(unsigned*)&a1);
            *(uint2*)&As[buf][rr[q]][kk[q] * 4] = ua;
            __nv_bfloat162 b0 = __floats2bfloat162_rn(rb[q].x, rb[q].y);
            __nv_bfloat162 b1 = __floats2bfloat162_rn(rb[q].z, rb[q].w);
            uint2 ub = make_uint2(*(unsigned*)&b0, *(unsigned*)&b1);
            *(uint2*)&Bs[buf][rr[q]][kk[q] * 4] = ub;
        }
    };

    ldg_chunk(0);
    sts_chunk(0);
    __syncthreads();
    int buf = 0;

    for (int kc = 0; kc < 32; kc++) {
        if (kc < 31) ldg_chunk(kc + 1);
        #pragma unroll
        for (int ks = 0; ks < 2; ks++) {
            wmma::fragment<wmma::matrix_a, 16, 16, 16, __nv_bfloat16, wmma::row_major> af[4];
            wmma::fragment<wmma::matrix_b, 16, 16, 16, __nv_bfloat16, wmma::col_major> bf[2];
            #pragma unroll
            for (int i = 0; i < 4; i++)
                wmma::load_matrix_sync(af[i], &As[buf][wm * 64 + i * 16][ks * 16], 40);
            #pragma unroll
            for (int j = 0; j < 2; j++)
                wmma::load_matrix_sync(bf[j], &Bs[buf][wn * 32 + j * 16][ks * 16], 40);
            #pragma unroll
            for (int i = 0; i < 4; i++)
                #pragma unroll
                for (int j = 0; j < 2; j++)
                    wmma::mma_sync(acc[i][j], af[i], bf[j], acc[i][j]);
        }
        if (kc < 31) {
            sts_chunk(buf ^ 1);
            __syncthreads();
            buf ^= 1;
        }
    }

    // store transposed: element (m, n) -> g_xq[(s*4096 + n)*128 + m]  (col-major, ld=128)
    #pragma unroll
    for (int i = 0; i < 4; i++)
        #pragma unroll
        for (int j = 0; j < 2; j++) {
            size_t ncol = (size_t)s * GDIM + nt * 128 + wn * 32 + j * 16;
            wmma::store_matrix_sync(g_xq + ncol * 128 + wm * 64 + i * 16,
                                    acc[i][j], 128, wmma::mem_col_major);
        }
}

// ---------------------------------------------------------------------------
// Kernel 2: persistent LSTM, bf16 GEMM + cp.async double-buffered h staging.
// 128 blocks x 256 threads; block owns 8 hidden cols (32 gate rows of W_hh
// resident in smem as bf16 for the whole sequence).
// ---------------------------------------------------------------------------
__device__ __forceinline__ void stage_chunk(__nv_bfloat16* dst,
                                            const __nv_bfloat16* hin,
                                            int c, int tid) {
    #pragma unroll
    for (int j = 0; j < 16; j++) {
        int slot = j * 256 + tid;
        int row = slot >> 5;          // 0..127
        int seg = slot & 31;          // 16B segment within 512B row chunk
        const __nv_bfloat16* src = hin + (size_t)row * HDIM + c * 256 + seg * 8;
        unsigned d = sptr(dst + row * HS_LD + seg * 8);
        asm volatile("cp.async.cg.shared.global [%0], [%1], 16;" :: "r"(d), "l"(src));
    }
}

__global__ __launch_bounds__(256, 1)
void lstm_persistent_kernel(const float* __restrict__ Whh,
                            const float* __restrict__ bih,
                            const float* __restrict__ bhh) {
    extern __shared__ __align__(16) unsigned char smem_raw[];
    __nv_bfloat16* Ws  = (__nv_bfloat16*)smem_raw;           // [32][WS_LD]
    __nv_bfloat16* Hs0 = Ws + 32 * WS_LD;                    // [128][HS_LD]
    __nv_bfloat16* Hs1 = Hs0 + 128 * HS_LD;
    float* Gs = (float*)Hs0;                                 // [128][GS_LD] epilogue overlay
    __shared__ float bsum[32];

    const int c0  = blockIdx.x * 8;
    const int tid = threadIdx.x;
    const int warp = tid >> 5;
    const int wm = warp >> 1;         // 0..3 -> 32 batch rows
    const int wn = warp & 1;          // 0..1 -> 16 gate cols

    // ---- W_hh slice -> bf16 smem (once) ----
    for (int i = tid; i < 32 * 256; i += 256) {
        int n = i >> 8, kv = i & 255;
        int g = n >> 3, col = n & 7;
        float4 v = *(const float4*)(Whh + (size_t)(g * HDIM + c0 + col) * HDIM + kv * 4);
        __nv_bfloat162 p0 = __floats2bfloat162_rn(v.x, v.y);
        __nv_bfloat162 p1 = __floats2bfloat162_rn(v.z, v.w);
        uint2 u = make_uint2(*(unsigned*)&p0, *(unsigned*)&p1);
        *(uint2*)&Ws[n * WS_LD + kv * 4] = u;
    }
    if (tid < 32) {
        int g = tid >> 3, col = tid & 7;
        int r = g * HDIM + c0 + col;
        bsum[tid] = bih[r] + bhh[r];
    }
    __syncthreads();

    for (int s = 0; s < SEQ; s++) {
        const __nv_bfloat16* hin = g_hb[s & 1];
        __nv_bfloat16*       hob = g_hb[(s + 1) & 1];

        wmma::fragment<wmma::accumulator, 16, 16, 16, float> acc[2];
        #pragma unroll
        for (int i = 0; i < 2; i++) wmma::fill_fragment(acc[i], 0.0f);

        stage_chunk(Hs0, hin, 0, tid);
        asm volatile("cp.async.commit_group;" ::: "memory");

        #pragma unroll
        for (int c = 0; c < 4; c++) {
            if (c < 3) {
                stage_chunk((c & 1) ? Hs0 : Hs1, hin, c + 1, tid);
                asm volatile("cp.async.commit_group;" ::: "memory");
                asm volatile("cp.async.wait_group 1;" ::: "memory");
            } else {
                asm volatile("cp.async.wait_group 0;" ::: "memory");
            }
            __syncthreads();

            const __nv_bfloat16* Hc = (c & 1) ? Hs1 : Hs0;
            #pragma unroll
            for (int ks = 0; ks < 16; ks++) {
                wmma::fragment<wmma::matrix_b, 16, 16, 16, __nv_bfloat16, wmma::col_major> bf;
                wmma::load_matrix_sync(bf, Ws + (wn * 16) * WS_LD + c * 256 + ks * 16, WS_LD);
                #pragma unroll
                for (int i = 0; i < 2; i++) {
                    wmma::fragment<wmma::matrix_a, 16, 16, 16, __nv_bfloat16, wmma::row_major> af;
                    wmma::load_matrix_sync(af, Hc + (wm * 32 + i * 16) * HS_LD + ks * 16, HS_LD);
                    wmma::mma_sync(acc[i], af, bf, acc[i]);
                }
            }
            __syncthreads();
        }

        // ---- epilogue: gates -> activations -> c/h ----
        #pragma unroll
        for (int i = 0; i < 2; i++)
            wmma::store_matrix_sync(Gs + (wm * 32 + i * 16) * GS_LD + wn * 16, acc[i],
                                    GS_LD, wmma::mem_row_major);
        __syncthreads();

        const float* xs = g_xq + (size_t)s * GDIM * BATCH;
        #pragma unroll
        for (int q = 0; q < 4; q++) {
            int cell = q * 256 + tid;
            int bl = cell & 127;
            int c  = cell >> 7;            // 0..7
            int hc = c0 + c;

            float gi = Gs[bl * GS_LD +      c] + xs[(size_t)(           hc) * BATCH + bl] + bsum[     c];
            float gf = Gs[bl * GS_LD +  8 + c] + xs[(size_t)(    HDIM + hc) * BATCH + bl] + bsum[ 8 + c];
            float gg = Gs[bl * GS_LD + 16 + c] + xs[(size_t)(2 * HDIM + hc) * BATCH + bl] + bsum[16 + c];
            float go = Gs[bl * GS_LD + 24 + c] + xs[(size_t)(3 * HDIM + hc) * BATCH + bl] + bsum[24 + c];

            float iv = 1.f / (1.f + expf(-gi));
            float fv = 1.f / (1.f + expf(-gf));
            float ov = 1.f / (1.f + expf(-go));

            int ci = hc * BATCH + bl;                 // transposed c: coalesced
            float cn = fv * g_c[ci] + iv * tanhf(gg);
            float hn = ov * tanhf(cn);
            g_c[ci] = cn;
            hob[(size_t)bl * HDIM + hc] = __float2bfloat16(hn);
            if (s == SEQ - 1) g_hf[(size_t)bl * HDIM + hc] = hn;
        }

        // ---- grid barrier ----
        if (s != SEQ - 1) {
            __syncthreads();
            if (tid == 0) {
                __threadfence();
                atomicAdd(&g_arrive, 1u);
                unsigned target = (unsigned)(s + 1) * (unsigned)GRID;
                while (atomicAdd(&g_arrive, 0u) < target) __nanosleep(64);
                __threadfence();
            }
            __syncthreads();
        }
    }
}

// ---------------------------------------------------------------------------
// Kernel 3: log_softmax over BATCH axis of final h [128, 1024] (fp32 shadow).
// ---------------------------------------------------------------------------
__global__ void logsoftmax_kernel(float* __restrict__ out) {
    const int hj = blockIdx.x;
    const int t  = threadIdx.x;   // 128

    float v = g_hf[(size_t)t * HDIM + hj];

    __shared__ float rm[4], rs[4];
    float m = v;
    #pragma unroll
    for (int o = 16; o; o >>= 1) m = fmaxf(m, __shfl_xor_sync(0xffffffffu, m, o));
    if ((t & 31) == 0) rm[t >> 5] = m;
    __syncthreads();
    m = fmaxf(fmaxf(rm[0], rm[1]), fmaxf(rm[2], rm[3]));

    float e = expf(v - m);
    float ssum = e;
    #pragma unroll
    for (int o = 16; o; o >>= 1) ssum += __shfl_xor_sync(0xffffffffu, ssum, o);
    if ((t & 31) == 0) rs[t >> 5] = ssum;
    __syncthreads();
    ssum = rs[0] + rs[1] + rs[2] + rs[3];

    out[(size_t)t * HDIM + hj] = (v - m) - logf(ssum);
}

// ---------------------------------------------------------------------------
extern "C" void kernel_launch(void* const* d_in, const int* in_sizes, int n_in,
                              void* d_out, int out_size) {
    (void)in_sizes; (void)n_in; (void)out_size;
    const int*   X    = (const int*)d_in[0];
    const float* embd = (const float*)d_in[1];
    const float* Wih  = (const float*)d_in[2];
    const float* Whh  = (const float*)d_in[3];
    const float* bih  = (const float*)d_in[4];
    const float* bhh  = (const float*)d_in[5];
    float* out = (float*)d_out;

    static int configured = 0;
    if (!configured) {
        cudaFuncSetAttribute(lstm_persistent_kernel,
                             cudaFuncAttributeMaxDynamicSharedMemorySize,
                             PERS_SMEM_BYTES);
        configured = 1;
    }

    zero_state_kernel<<<512, 256>>>();
    embed_proj_kernel<<<dim3(32, 512), 256>>>(X, embd, Wih);
    lstm_persistent_kernel<<<GRID, 256, PERS_SMEM_BYTES>>>(Whh, bih, bhh);
    logsoftmax_kernel<<<HDIM, BATCH>>>(out);
}